// round 16
// baseline (speedup 1.0000x reference)
#include <cuda_runtime.h>
#include <cuda_bf16.h>
#include <math.h>
#include <stdint.h>

// ---------------------------------------------------------------------------
#define BATCH 8
#define SEQ   256
#define NTOK  2048
#define DD    1152
#define DD2   576
#define DD3   3456
#define DD4   4608
#define MH    4608
#define MH2   2304
#define NE    8
#define NH    16
#define HD    72
#define LN_EPS 1e-6f

// ---------------------------------------------------------------------------
// Device scratch (no allocations allowed)
// ---------------------------------------------------------------------------
__device__ __align__(16) float g_mod[BATCH * DD4];
__device__ __align__(16) float g_qkv[NTOK * DD3];
__device__ __align__(16) float g_nx[NTOK * DD];
__device__ float g_score[NTOK * 2];
__device__ float g_slot_score[NTOK * 2];
__device__ int   g_topidx[NTOK * 2];
__device__ int   g_bucket_tok[NTOK * 2];
__device__ int   g_off[NE];
__device__ int   g_cnt[NE];
// packed bf16x2 (k-pair) hi/lo activations
__device__ __align__(16) unsigned g_hh [(size_t)NTOK * DD2];
__device__ __align__(16) unsigned g_hl [(size_t)NTOK * DD2];
__device__ __align__(16) unsigned g_aoh[(size_t)NTOK * DD2];
__device__ __align__(16) unsigned g_aol[(size_t)NTOK * DD2];
__device__ __align__(16) unsigned g_nxh[(size_t)NTOK * DD2];
__device__ __align__(16) unsigned g_nxl[(size_t)NTOK * DD2];
__device__ __align__(16) unsigned g_h1h[(size_t)NTOK * 2 * MH2];
__device__ __align__(16) unsigned g_h1l[(size_t)NTOK * 2 * MH2];
// packed bf16x2 hi/lo weights, [K/2][N] per expert
__device__ __align__(16) unsigned g_qkvh[(size_t)DD2 * DD3];
__device__ __align__(16) unsigned g_qkvl[(size_t)DD2 * DD3];
__device__ __align__(16) unsigned g_projh[(size_t)DD2 * DD];
__device__ __align__(16) unsigned g_projl[(size_t)DD2 * DD];
__device__ __align__(16) unsigned g_w1h[(size_t)NE * DD2 * MH];
__device__ __align__(16) unsigned g_w1l[(size_t)NE * DD2 * MH];
__device__ __align__(16) unsigned g_w2h[(size_t)NE * MH2 * DD];
__device__ __align__(16) unsigned g_w2l[(size_t)NE * MH2 * DD];

// ---------------------------------------------------------------------------
// Helpers
// ---------------------------------------------------------------------------
__device__ __forceinline__ void mma_bf16(float* d, const unsigned* a, const unsigned* b) {
    asm("mma.sync.aligned.m16n8k16.row.col.f32.bf16.bf16.f32 "
        "{%0,%1,%2,%3}, {%4,%5,%6,%7}, {%8,%9}, {%0,%1,%2,%3};"
        : "+f"(d[0]), "+f"(d[1]), "+f"(d[2]), "+f"(d[3])
        : "r"(a[0]), "r"(a[1]), "r"(a[2]), "r"(a[3]), "r"(b[0]), "r"(b[1]));
}
__device__ __forceinline__ void ldm4(unsigned* r, unsigned addr) {
    asm("ldmatrix.sync.aligned.m8n8.x4.shared.b16 {%0,%1,%2,%3}, [%4];"
        : "=r"(r[0]), "=r"(r[1]), "=r"(r[2]), "=r"(r[3]) : "r"(addr));
}
__device__ __forceinline__ void cpa16(unsigned dst, const void* src) {
    asm volatile("cp.async.cg.shared.global [%0], [%1], 16;" :: "r"(dst), "l"(src));
}
__device__ __forceinline__ void cpa_commit() {
    asm volatile("cp.async.commit_group;" ::: "memory");
}
__device__ __forceinline__ unsigned smem_u32(const void* p) {
    unsigned a;
    asm("{ .reg .u64 t; cvta.to.shared.u64 t, %1; cvt.u32.u64 %0, t; }"
        : "=r"(a) : "l"(p));
    return a;
}
__device__ __forceinline__ float gelu_tanh(float x) {
    float x3 = x * x * x;
    return 0.5f * x * (1.f + tanhf(0.7978845608028654f * (x + 0.044715f * x3)));
}
__device__ __forceinline__ void splitpack2(float x0, float x1, unsigned& h, unsigned& l) {
    __nv_bfloat16 h0 = __float2bfloat16_rn(x0);
    __nv_bfloat16 h1 = __float2bfloat16_rn(x1);
    float r0 = x0 - __bfloat162float(h0);
    float r1 = x1 - __bfloat162float(h1);
    __nv_bfloat16 l0 = __float2bfloat16_rn(r0);
    __nv_bfloat16 l1 = __float2bfloat16_rn(r1);
    h = ((unsigned)__bfloat16_as_ushort(h1) << 16) | __bfloat16_as_ushort(h0);
    l = ((unsigned)__bfloat16_as_ushort(l1) << 16) | __bfloat16_as_ushort(l0);
}

// ---------------------------------------------------------------------------
// Weight pre-split (vectorized)
// ---------------------------------------------------------------------------
__global__ void pack_w(const float* __restrict__ w, unsigned* __restrict__ hi,
                       unsigned* __restrict__ lo, int K2, int N) {
    int e = blockIdx.z;
    w  += (size_t)e * K2 * 2 * N;
    hi += (size_t)e * K2 * N;
    lo += (size_t)e * K2 * N;
    int n4 = blockIdx.x * 256 + threadIdx.x;
    int k2 = blockIdx.y;
    if (n4 * 4 >= N) return;
    float4 x0 = *(const float4*)(w + (size_t)(2 * k2) * N + n4 * 4);
    float4 x1 = *(const float4*)(w + (size_t)(2 * k2 + 1) * N + n4 * 4);
    uint4 h, l;
    splitpack2(x0.x, x1.x, h.x, l.x);
    splitpack2(x0.y, x1.y, h.y, l.y);
    splitpack2(x0.z, x1.z, h.z, l.z);
    splitpack2(x0.w, x1.w, h.w, l.w);
    *(uint4*)(hi + (size_t)k2 * N + n4 * 4) = h;
    *(uint4*)(lo + (size_t)k2 * N + n4 * 4) = l;
}

// ---------------------------------------------------------------------------
// adaLN modulation
// ---------------------------------------------------------------------------
__global__ void adaln_kernel(const float* __restrict__ c,
                             const float* __restrict__ w,
                             const float* __restrict__ b) {
    int bb = blockIdx.y;
    int col = blockIdx.x * 128 + threadIdx.x;
    __shared__ float cs[DD];
    for (int i = threadIdx.x; i < DD; i += 128) {
        float v = c[bb * DD + i];
        cs[i] = v / (1.f + __expf(-v));
    }
    __syncthreads();
    float acc = b[col];
    #pragma unroll 4
    for (int i = 0; i < DD; i++)
        acc += cs[i] * w[(size_t)i * DD4 + col];
    g_mod[bb * DD4 + col] = acc;
}

// ---------------------------------------------------------------------------
// LayerNorm
// ---------------------------------------------------------------------------
template <int MODE>
__global__ void ln_kernel(const float* __restrict__ in) {
    int t = blockIdx.x;
    const float* xr = in + (size_t)t * DD;
    int tid = threadIdx.x, lane = tid & 31, warp = tid >> 5;
    float s = 0.f, s2 = 0.f;
    for (int i = tid; i < DD; i += 256) { float v = xr[i]; s += v; s2 += v * v; }
    #pragma unroll
    for (int o = 16; o; o >>= 1) {
        s  += __shfl_xor_sync(0xffffffffu, s,  o);
        s2 += __shfl_xor_sync(0xffffffffu, s2, o);
    }
    __shared__ float ws[8], ws2[8], mean_s, rstd_s;
    if (lane == 0) { ws[warp] = s; ws2[warp] = s2; }
    __syncthreads();
    if (warp == 0) {
        s  = (lane < 8) ? ws[lane]  : 0.f;
        s2 = (lane < 8) ? ws2[lane] : 0.f;
        #pragma unroll
        for (int o = 4; o; o >>= 1) {
            s  += __shfl_xor_sync(0xffffffffu, s,  o);
            s2 += __shfl_xor_sync(0xffffffffu, s2, o);
        }
        if (lane == 0) {
            float m = s * (1.f / DD);
            float v = s2 * (1.f / DD) - m * m;
            mean_s = m; rstd_s = rsqrtf(v + LN_EPS);
        }
    }
    __syncthreads();
    float m = mean_s, rstd = rstd_s;
    int bb = t >> 8;
    for (int i2 = tid; i2 < DD2; i2 += 256) {
        float v0 = (xr[2 * i2]     - m) * rstd;
        float v1 = (xr[2 * i2 + 1] - m) * rstd;
        if (MODE == 0) {
            const float* sc = g_mod + bb * DD4 + DD;
            const float* sh = g_mod + bb * DD4;
            v0 = v0 * (1.f + sc[2 * i2])     + sh[2 * i2];
            v1 = v1 * (1.f + sc[2 * i2 + 1]) + sh[2 * i2 + 1];
            unsigned h, l;
            splitpack2(v0, v1, h, l);
            g_hh[(size_t)t * DD2 + i2] = h;
            g_hl[(size_t)t * DD2 + i2] = l;
        } else {
            g_nx[(size_t)t * DD + 2 * i2]     = v0;
            g_nx[(size_t)t * DD + 2 * i2 + 1] = v1;
            unsigned h, l;
            splitpack2(v0, v1, h, l);
            g_nxh[(size_t)t * DD2 + i2] = h;
            g_nxl[(size_t)t * DD2 + i2] = l;
        }
    }
}

// ---------------------------------------------------------------------------
// bf16x3 GEMM, templated M-tile (128 or 64). cp.async, ldmatrix, 2 CTAs/SM.
// MODE 0: g_qkv = A @ qkv_w + b
// MODE 1: out = xres + gate_msa*(A@proj + b)
// MODE 2: g_h1(packed) = gelu(gather(nx)@w1 + b1)
// MODE 3: out[tok] += gate_mlp*score*(h1@w2 + b2)   (fused combine, atomic)
// ---------------------------------------------------------------------------
#define A_STRIDE 20
#define B_STRIDE 136
#define B_WORDS 2176   // 16 * 136

template <int MODE, int MTILE>
__global__ __launch_bounds__(256, 2)
void gemm_tc(const unsigned* __restrict__ Ah, const unsigned* __restrict__ Al,
             const unsigned* __restrict__ Wh, const unsigned* __restrict__ Wl,
             const float* __restrict__ bias,
             const float* __restrict__ xres, float* __restrict__ Cout,
             int M, int Nn, int Kk) {
    constexpr int A_WORDS = MTILE * A_STRIDE;
    constexpr int AL_OFF = A_WORDS;
    constexpr int BH_OFF = 2 * A_WORDS;
    constexpr int BL_OFF = 2 * A_WORDS + B_WORDS;
    constexpr int BUFW   = 2 * A_WORDS + 2 * B_WORDS;
    constexpr int MI = MTILE / 32;

    int e = blockIdx.z;
    const int* gather = nullptr;
    int rowbase = 0;
    float* C = Cout;

    if (MODE == 2) {
        M = g_cnt[e]; rowbase = g_off[e];
        gather = g_bucket_tok + rowbase;
        Wh += (size_t)e * DD2 * MH;
        Wl += (size_t)e * DD2 * MH;
        bias += e * MH;
    } else if (MODE == 3) {
        M = g_cnt[e]; rowbase = g_off[e];
        Ah += (size_t)rowbase * MH2;
        Al += (size_t)rowbase * MH2;
        Wh += (size_t)e * MH2 * DD;
        Wl += (size_t)e * MH2 * DD;
        bias += e * DD;
    } else if (MODE == 0) {
        C = g_qkv;
    }

    int row0 = blockIdx.y * MTILE;
    if (row0 >= M) return;
    int col0 = blockIdx.x * 128;

    extern __shared__ __align__(16) unsigned smu[];
    unsigned sb = smem_u32(smu);
    int K2 = Kk / 2;

    int tid = threadIdx.x;
    int lane = tid & 31, wid = tid >> 5;
    int gid = lane >> 2, tig = lane & 3;
    int wm = wid >> 2, wn = wid & 3;

    int r_a, sa;
    if (MTILE == 128) { r_a = tid >> 1; sa = (tid & 1) * 2; }
    else              { r_a = tid >> 2; sa = tid & 3; }
    int gr = row0 + r_a;
    if (gr > M - 1) gr = M - 1;
    size_t arow = (size_t)((MODE == 2) ? gather[gr] : gr) * K2;
    const unsigned* aSrcH = Ah + arow + sa * 4;
    const unsigned* aSrcL = Al + arow + sa * 4;
    unsigned aDstH = sb + (r_a * A_STRIDE + sa * 4) * 4;
    unsigned aDstL = sb + (AL_OFF + r_a * A_STRIDE + sa * 4) * 4;
    int r_b = tid >> 4, sbg = (tid & 15) * 2;
    const unsigned* bSrcH = Wh + (size_t)r_b * Nn + col0 + sbg * 4;
    const unsigned* bSrcL = Wl + (size_t)r_b * Nn + col0 + sbg * 4;
    unsigned bDstH = sb + (BH_OFF + r_b * B_STRIDE + sbg * 4) * 4;
    unsigned bDstL = sb + (BL_OFF + r_b * B_STRIDE + sbg * 4) * 4;

    float acc[MI][4][4];
    #pragma unroll
    for (int mi = 0; mi < MI; mi++)
        #pragma unroll
        for (int ni = 0; ni < 4; ni++)
            #pragma unroll
            for (int r = 0; r < 4; r++) acc[mi][ni][r] = 0.f;

    int nch = Kk / 32;
    {
        if (MTILE == 128) {
            cpa16(aDstH,      aSrcH);     cpa16(aDstH + 16, aSrcH + 4);
            cpa16(aDstL,      aSrcL);     cpa16(aDstL + 16, aSrcL + 4);
        } else {
            cpa16(aDstH, aSrcH);
            cpa16(aDstL, aSrcL);
        }
        cpa16(bDstH,      bSrcH);     cpa16(bDstH + 16, bSrcH + 4);
        cpa16(bDstL,      bSrcL);     cpa16(bDstL + 16, bSrcL + 4);
        cpa_commit();
    }

    int lrow = lane & 15;
    int lk = ((lane >> 4) & 1) * 4;
    unsigned aBaseH = sb + ((wm * (MTILE / 2) + lrow) * A_STRIDE + lk) * 4;

    for (int c = 0; c < nch; c++) {
        int cur = c & 1;
        bool more = (c + 1 < nch);
        if (more) {
            unsigned bo = (cur ^ 1) * (BUFW * 4);
            size_t ao = (size_t)(c + 1) * 16;
            size_t wo = (size_t)(c + 1) * 16 * Nn;
            if (MTILE == 128) {
                cpa16(aDstH + bo,      aSrcH + ao);  cpa16(aDstH + bo + 16, aSrcH + ao + 4);
                cpa16(aDstL + bo,      aSrcL + ao);  cpa16(aDstL + bo + 16, aSrcL + ao + 4);
            } else {
                cpa16(aDstH + bo, aSrcH + ao);
                cpa16(aDstL + bo, aSrcL + ao);
            }
            cpa16(bDstH + bo,      bSrcH + wo);  cpa16(bDstH + bo + 16, bSrcH + wo + 4);
            cpa16(bDstL + bo,      bSrcL + wo);  cpa16(bDstL + bo + 16, bSrcL + wo + 4);
            cpa_commit();
            asm volatile("cp.async.wait_group 1;" ::: "memory");
        } else {
            asm volatile("cp.async.wait_group 0;" ::: "memory");
        }
        __syncthreads();

        unsigned bufb = cur * (BUFW * 4);
        const unsigned* Bh = smu + cur * BUFW + BH_OFF;
        const unsigned* Bl = smu + cur * BUFW + BL_OFF;
        #pragma unroll
        for (int kb = 0; kb < 2; kb++) {
            unsigned afh[MI][4], afl[MI][4];
            unsigned bfh[4][2], bfl[4][2];
            #pragma unroll
            for (int mi = 0; mi < MI; mi++) {
                unsigned a = aBaseH + bufb + kb * 32 + mi * (16 * A_STRIDE * 4);
                ldm4(afh[mi], a);
                ldm4(afl[mi], a + AL_OFF * 4);
            }
            #pragma unroll
            for (int ni = 0; ni < 4; ni++) {
                int n = wn * 32 + ni * 8 + gid;
                int j0 = (kb * 8 + tig) * B_STRIDE + n;
                int j1 = (kb * 8 + tig + 4) * B_STRIDE + n;
                bfh[ni][0] = Bh[j0]; bfh[ni][1] = Bh[j1];
                bfl[ni][0] = Bl[j0]; bfl[ni][1] = Bl[j1];
            }
            #pragma unroll
            for (int mi = 0; mi < MI; mi++)
                #pragma unroll
                for (int ni = 0; ni < 4; ni++)
                    mma_bf16(acc[mi][ni], afl[mi], bfh[ni]);
            #pragma unroll
            for (int mi = 0; mi < MI; mi++)
                #pragma unroll
                for (int ni = 0; ni < 4; ni++)
                    mma_bf16(acc[mi][ni], afh[mi], bfl[ni]);
            #pragma unroll
            for (int mi = 0; mi < MI; mi++)
                #pragma unroll
                for (int ni = 0; ni < 4; ni++)
                    mma_bf16(acc[mi][ni], afh[mi], bfh[ni]);
        }
        __syncthreads();
    }

    #pragma unroll
    for (int mi = 0; mi < MI; mi++) {
        int mloc = row0 + wm * (MTILE / 2) + mi * 16 + gid;
        #pragma unroll
        for (int half = 0; half < 2; half++) {
            int m = mloc + half * 8;
            if (m >= M) continue;
            #pragma unroll
            for (int ni = 0; ni < 4; ni++) {
                int n = col0 + wn * 32 + ni * 8 + tig * 2;
                float ox = acc[mi][ni][half * 2 + 0] + bias[n];
                float oy = acc[mi][ni][half * 2 + 1] + bias[n + 1];
                if (MODE == 1) {
                    int bb = m >> 8;
                    const float* gm = g_mod + bb * DD4 + 2 * DD + n;
                    const float* rx = xres + (size_t)m * DD + n;
                    ox = rx[0] + gm[0] * ox;
                    oy = rx[1] + gm[1] * oy;
                    *(float2*)(C + (size_t)m * Nn + n) = make_float2(ox, oy);
                } else if (MODE == 2) {
                    ox = gelu_tanh(ox);
                    oy = gelu_tanh(oy);
                    unsigned h, l;
                    splitpack2(ox, oy, h, l);
                    size_t idx = (size_t)(rowbase + m) * (Nn / 2) + (n >> 1);
                    g_h1h[idx] = h;
                    g_h1l[idx] = l;
                } else if (MODE == 3) {
                    int slot = rowbase + m;
                    int t = g_bucket_tok[slot];
                    float s = g_slot_score[slot];
                    int bb = t >> 8;
                    const float* gm = g_mod + bb * DD4 + 3 * DD + n;
                    float* op = C + (size_t)t * DD + n;
                    atomicAdd(op,     s * gm[0] * ox);
                    atomicAdd(op + 1, s * gm[1] * oy);
                } else {
                    *(float2*)(C + (size_t)m * Nn + n) = make_float2(ox, oy);
                }
            }
        }
    }
}

// ---------------------------------------------------------------------------
// Attention, register-tiled; writes packed bf16 hi/lo output directly.
// ---------------------------------------------------------------------------
#define KV_STRIDE 74
#define ATTN_SMEM ((2 * 256 * KV_STRIDE + 8 * 4 * 256) * 4)   // 184320 B

__global__ void attn_kernel() {
    int h = blockIdx.x, b = blockIdx.y, z = blockIdx.z;
    extern __shared__ float smn[];
    float* Ks = smn;
    float* Vs = smn + 256 * KV_STRIDE;
    float* Ps = smn + 2 * 256 * KV_STRIDE;

    const float* base = g_qkv + (size_t)b * SEQ * DD3;
    int tid = threadIdx.x;
    for (int i = tid; i < SEQ * (HD / 2); i += 256) {
        int r = i / (HD / 2), d2 = i - r * (HD / 2);
        size_t g = (size_t)r * DD3 + h * HD + 2 * d2;
        *(float2*)(Ks + r * KV_STRIDE + 2 * d2) = make_float2(base[g + DD],     base[g + DD + 1]);
        *(float2*)(Vs + r * KV_STRIDE + 2 * d2) = make_float2(base[g + 2 * DD], base[g + 2 * DD + 1]);
    }
    __syncthreads();

    int warp = tid >> 5, lane = tid & 31;
    float* ps = Ps + warp * 4 * 256;
    const float scale = 0.11785113019775793f;
    int qbase = z * 128;

    #pragma unroll
    for (int j = 0; j < 4; j++) {
        int q0 = qbase + warp * 4 + j * 32;

        float acc[4][8];
        #pragma unroll
        for (int i = 0; i < 4; i++)
            #pragma unroll
            for (int kk = 0; kk < 8; kk++) acc[i][kk] = 0.f;

        const float* q0p = base + (size_t)q0 * DD3 + h * HD;
        for (int d2 = 0; d2 < HD / 2; d2++) {
            float2 kd[8];
            #pragma unroll
            for (int kk = 0; kk < 8; kk++)
                kd[kk] = *(const float2*)(Ks + (lane + kk * 32) * KV_STRIDE + 2 * d2);
            float2 qd[4];
            #pragma unroll
            for (int i = 0; i < 4; i++)
                qd[i] = *(const float2*)(q0p + (size_t)i * DD3 + 2 * d2);
            #pragma unroll
            for (int i = 0; i < 4; i++)
                #pragma unroll
                for (int kk = 0; kk < 8; kk++)
                    acc[i][kk] += qd[i].x * kd[kk].x + qd[i].y * kd[kk].y;
        }

        #pragma unroll
        for (int i = 0; i < 4; i++) {
            float mx = -1e30f;
            #pragma unroll
            for (int kk = 0; kk < 8; kk++) {
                acc[i][kk] *= scale;
                mx = fmaxf(mx, acc[i][kk]);
            }
            #pragma unroll
            for (int o = 16; o; o >>= 1) mx = fmaxf(mx, __shfl_xor_sync(0xffffffffu, mx, o));
            float sum = 0.f;
            #pragma unroll
            for (int kk = 0; kk < 8; kk++) { acc[i][kk] = __expf(acc[i][kk] - mx); sum += acc[i][kk]; }
            #pragma unroll
            for (int o = 16; o; o >>= 1) sum += __shfl_xor_sync(0xffffffffu, sum, o);
            float inv = 1.f / sum;
            #pragma unroll
            for (int kk = 0; kk < 8; kk++) ps[i * 256 + lane + kk * 32] = acc[i][kk] * inv;
        }
        __syncwarp();

        float o0[4], o1[4], o2[4];
        #pragma unroll
        for (int i = 0; i < 4; i++) { o0[i] = 0.f; o1[i] = 0.f; o2[i] = 0.f; }
        for (int k = 0; k < SEQ; k++) {
            const float* vr = Vs + k * KV_STRIDE;
            float v0 = vr[lane];
            float v1 = vr[lane + 32];
            float v2 = (lane < 8) ? vr[lane + 64] : 0.f;
            #pragma unroll
            for (int i = 0; i < 4; i++) {
                float p = ps[i * 256 + k];
                o0[i] += p * v0;
                o1[i] += p * v1;
                o2[i] += p * v2;
            }
        }
        #pragma unroll
        for (int i = 0; i < 4; i++) {
            float p0 = __shfl_xor_sync(0xffffffffu, o0[i], 1);
            float p1 = __shfl_xor_sync(0xffffffffu, o1[i], 1);
            float p2 = __shfl_xor_sync(0xffffffffu, o2[i], 1);
            if ((lane & 1) == 0) {
                size_t rb = (size_t)(b * SEQ + q0 + i) * DD2 + h * (HD / 2);
                unsigned hw, lw;
                splitpack2(o0[i], p0, hw, lw);
                g_aoh[rb + (lane >> 1)] = hw;
                g_aol[rb + (lane >> 1)] = lw;
                splitpack2(o1[i], p1, hw, lw);
                g_aoh[rb + 16 + (lane >> 1)] = hw;
                g_aol[rb + 16 + (lane >> 1)] = lw;
                if (lane < 8) {
                    splitpack2(o2[i], p2, hw, lw);
                    g_aoh[rb + 32 + (lane >> 1)] = hw;
                    g_aol[rb + 32 + (lane >> 1)] = lw;
                }
            }
        }
        __syncwarp();
    }
}

// ---------------------------------------------------------------------------
// Router
// ---------------------------------------------------------------------------
__global__ void router_kernel(const float* __restrict__ gw,
                              const float* __restrict__ gb) {
    int t = blockIdx.x * 8 + (threadIdx.x >> 5);
    int lane = threadIdx.x & 31;
    const float* xr = g_nx + (size_t)t * DD;
    float acc[NE];
    #pragma unroll
    for (int e = 0; e < NE; e++) acc[e] = 0.f;
    for (int i = lane; i < DD; i += 32) {
        float v = xr[i];
        const float* g = gw + i * NE;
        #pragma unroll
        for (int e = 0; e < NE; e++) acc[e] += v * g[e];
    }
    #pragma unroll
    for (int e = 0; e < NE; e++)
        #pragma unroll
        for (int o = 16; o; o >>= 1) acc[e] += __shfl_xor_sync(0xffffffffu, acc[e], o);
    if (lane == 0) {
        float best = -1e30f, second = -1e30f; int bi = 0, si = 0;
        #pragma unroll
        for (int e = 0; e < NE; e++) {
            float v = acc[e] + gb[e];
            if (v > best) { second = best; si = bi; best = v; bi = e; }
            else if (v > second) { second = v; si = e; }
        }
        float e1 = __expf(second - best);
        float inv = 1.f / (1.f + e1);
        g_topidx[t * 2] = bi;  g_topidx[t * 2 + 1] = si;
        g_score[t * 2] = inv;  g_score[t * 2 + 1] = e1 * inv;
    }
}

// ---------------------------------------------------------------------------
// Bucketize (also writes slot -> score map)
// ---------------------------------------------------------------------------
__global__ void bucketize_kernel() {
    __shared__ int cnt[NE], off[NE], cur[NE];
    int tid = threadIdx.x;
    if (tid < NE) cnt[tid] = 0;
    __syncthreads();
    for (int t = tid; t < NTOK; t += 256) {
        atomicAdd(&cnt[g_topidx[t * 2]], 1);
        atomicAdd(&cnt[g_topidx[t * 2 + 1]], 1);
    }
    __syncthreads();
    if (tid == 0) {
        int o = 0;
        for (int e = 0; e < NE; e++) {
            off[e] = o; g_off[e] = o; g_cnt[e] = cnt[e];
            o += cnt[e];
        }
    }
    __syncthreads();
    if (tid < NE) cur[tid] = off[tid];
    __syncthreads();
    for (int t = tid; t < NTOK; t += 256) {
        #pragma unroll
        for (int k = 0; k < 2; k++) {
            int e = g_topidx[t * 2 + k];
            int p = atomicAdd(&cur[e], 1);
            g_bucket_tok[p] = t;
            g_slot_score[p] = g_score[t * 2 + k];
        }
    }
}

// ---------------------------------------------------------------------------
// Launcher (two-stream overlap: w1/w2 packing runs concurrently with the
// attention phase; joined before MoE GEMM1)
// ---------------------------------------------------------------------------
#define GEMM_SMEM_128 (2 * (2 * (128 * A_STRIDE) + 2 * B_WORDS) * 4)  // 75776
#define GEMM_SMEM_64  (2 * (2 * (64 * A_STRIDE) + 2 * B_WORDS) * 4)   // 55296

extern "C" void kernel_launch(void* const* d_in, const int* in_sizes, int n_in,
                              void* d_out, int out_size) {
    (void)in_sizes; (void)n_in; (void)out_size;
    const float* x       = (const float*)d_in[0];
    const float* c       = (const float*)d_in[1];
    const float* qkv_w   = (const float*)d_in[2];
    const float* qkv_b   = (const float*)d_in[3];
    const float* proj_w  = (const float*)d_in[4];
    const float* proj_b  = (const float*)d_in[5];
    const float* adaln_w = (const float*)d_in[6];
    const float* adaln_b = (const float*)d_in[7];
    const float* gate_w  = (const float*)d_in[8];
    const float* gate_b  = (const float*)d_in[9];
    const float* w1      = (const float*)d_in[10];
    const float* b1      = (const float*)d_in[11];
    const float* w2      = (const float*)d_in[12];
    const float* b2      = (const float*)d_in[13];
    float* out = (float*)d_out;

    // one-time handle creation (handles only; captured work identical per call)
    static cudaStream_t s2 = nullptr;
    static cudaEvent_t evF = nullptr, evJ = nullptr;
    if (s2 == nullptr) {
        cudaStreamCreateWithFlags(&s2, cudaStreamNonBlocking);
        cudaEventCreateWithFlags(&evF, cudaEventDisableTiming);
        cudaEventCreateWithFlags(&evJ, cudaEventDisableTiming);
    }

    cudaFuncSetAttribute(attn_kernel, cudaFuncAttributeMaxDynamicSharedMemorySize, ATTN_SMEM);
    cudaFuncSetAttribute(gemm_tc<0,128>, cudaFuncAttributeMaxDynamicSharedMemorySize, GEMM_SMEM_128);
    cudaFuncSetAttribute(gemm_tc<1,64>,  cudaFuncAttributeMaxDynamicSharedMemorySize, GEMM_SMEM_64);
    cudaFuncSetAttribute(gemm_tc<2,128>, cudaFuncAttributeMaxDynamicSharedMemorySize, GEMM_SMEM_128);
    cudaFuncSetAttribute(gemm_tc<3,64>,  cudaFuncAttributeMaxDynamicSharedMemorySize, GEMM_SMEM_64);

    unsigned *qkvh, *qkvl, *projh, *projl, *w1h, *w1l, *w2h, *w2l;
    unsigned *hh, *hl, *aoh, *aol, *nxh, *nxl, *h1h, *h1l;
    cudaGetSymbolAddress((void**)&qkvh, g_qkvh);
    cudaGetSymbolAddress((void**)&qkvl, g_qkvl);
    cudaGetSymbolAddress((void**)&projh, g_projh);
    cudaGetSymbolAddress((void**)&projl, g_projl);
    cudaGetSymbolAddress((void**)&w1h, g_w1h);
    cudaGetSymbolAddress((void**)&w1l, g_w1l);
    cudaGetSymbolAddress((void**)&w2h, g_w2h);
    cudaGetSymbolAddress((void**)&w2l, g_w2l);
    cudaGetSymbolAddress((void**)&hh, g_hh);
    cudaGetSymbolAddress((void**)&hl, g_hl);
    cudaGetSymbolAddress((void**)&aoh, g_aoh);
    cudaGetSymbolAddress((void**)&aol, g_aol);
    cudaGetSymbolAddress((void**)&nxh, g_nxh);
    cudaGetSymbolAddress((void**)&nxl, g_nxl);
    cudaGetSymbolAddress((void**)&h1h, g_h1h);
    cudaGetSymbolAddress((void**)&h1l, g_h1l);

    // fork: big weight packs on side stream
    cudaEventRecord(evF, 0);
    cudaStreamWaitEvent(s2, evF, 0);
    pack_w<<<dim3((MH / 4 + 255) / 256, DD2, NE), 256, 0, s2>>>(w1, w1h, w1l, DD2, MH);
    pack_w<<<dim3((DD / 4 + 255) / 256, MH2, NE), 256, 0, s2>>>(w2, w2h, w2l, MH2, DD);
    cudaEventRecord(evJ, s2);

    // main stream
    pack_w<<<dim3((DD3 / 4 + 255) / 256, DD2, 1), 256>>>(qkv_w, qkvh, qkvl, DD2, DD3);
    pack_w<<<dim3((DD / 4 + 255) / 256, DD2, 1),  256>>>(proj_w, projh, projl, DD2, DD);
    adaln_kernel<<<dim3(DD4 / 128, BATCH), 128>>>(c, adaln_w, adaln_b);
    ln_kernel<0><<<NTOK, 256>>>(x);
    gemm_tc<0,128><<<dim3(DD3 / 128, NTOK / 128, 1), 256, GEMM_SMEM_128>>>(
        hh, hl, qkvh, qkvl, qkv_b, nullptr, nullptr, NTOK, DD3, DD);
    attn_kernel<<<dim3(NH, BATCH, 2), 256, ATTN_SMEM>>>();
    gemm_tc<1,64><<<dim3(DD / 128, NTOK / 64, 1), 256, GEMM_SMEM_64>>>(
        aoh, aol, projh, projl, proj_b, x, out, NTOK, DD, DD);
    ln_kernel<1><<<NTOK, 256>>>(out);
    router_kernel<<<NTOK / 8, 256>>>(gate_w, gate_b);
    bucketize_kernel<<<1, 256>>>();

    // join before MoE GEMMs consume w1/w2 packs
    cudaStreamWaitEvent(0, evJ, 0);
    gemm_tc<2,128><<<dim3(MH / 128, NTOK * 2 / 128, NE), 256, GEMM_SMEM_128>>>(
        nxh, nxl, w1h, w1l, b1, nullptr, nullptr, 0, MH, DD);
    gemm_tc<3,64><<<dim3(DD / 128, NTOK * 2 / 64, NE), 256, GEMM_SMEM_64>>>(
        h1h, h1l, w2h, w2l, b2, nullptr, out, 0, DD, MH);
}

// round 17
// speedup vs baseline: 1.0071x; 1.0071x over previous
#include <cuda_runtime.h>
#include <cuda_bf16.h>
#include <math.h>
#include <stdint.h>

// ---------------------------------------------------------------------------
#define BATCH 8
#define SEQ   256
#define NTOK  2048
#define DD    1152
#define DD2   576
#define DD3   3456
#define DD4   4608
#define MH    4608
#define MH2   2304
#define NE    8
#define NH    16
#define HD    72
#define LN_EPS 1e-6f

// ---------------------------------------------------------------------------
// Device scratch (no allocations allowed)
// ---------------------------------------------------------------------------
__device__ __align__(16) float g_mod[BATCH * DD4];
__device__ __align__(16) float g_qkv[NTOK * DD3];
__device__ float g_score[NTOK * 2];
__device__ float g_slot_score[NTOK * 2];
__device__ int   g_topidx[NTOK * 2];
__device__ int   g_bucket_tok[NTOK * 2];
__device__ int   g_off[NE];
__device__ int   g_cnt[NE];
// packed bf16x2 (k-pair) hi/lo activations
__device__ __align__(16) unsigned g_hh [(size_t)NTOK * DD2];
__device__ __align__(16) unsigned g_hl [(size_t)NTOK * DD2];
__device__ __align__(16) unsigned g_aoh[(size_t)NTOK * DD2];
__device__ __align__(16) unsigned g_aol[(size_t)NTOK * DD2];
__device__ __align__(16) unsigned g_nxh[(size_t)NTOK * DD2];
__device__ __align__(16) unsigned g_nxl[(size_t)NTOK * DD2];
__device__ __align__(16) unsigned g_h1h[(size_t)NTOK * 2 * MH2];
__device__ __align__(16) unsigned g_h1l[(size_t)NTOK * 2 * MH2];
// packed bf16x2 hi/lo weights, [K/2][N] per expert
__device__ __align__(16) unsigned g_qkvh[(size_t)DD2 * DD3];
__device__ __align__(16) unsigned g_qkvl[(size_t)DD2 * DD3];
__device__ __align__(16) unsigned g_projh[(size_t)DD2 * DD];
__device__ __align__(16) unsigned g_projl[(size_t)DD2 * DD];
__device__ __align__(16) unsigned g_w1h[(size_t)NE * DD2 * MH];
__device__ __align__(16) unsigned g_w1l[(size_t)NE * DD2 * MH];
__device__ __align__(16) unsigned g_w2h[(size_t)NE * MH2 * DD];
__device__ __align__(16) unsigned g_w2l[(size_t)NE * MH2 * DD];

// ---------------------------------------------------------------------------
// Helpers
// ---------------------------------------------------------------------------
__device__ __forceinline__ void mma_bf16(float* d, const unsigned* a, const unsigned* b) {
    asm("mma.sync.aligned.m16n8k16.row.col.f32.bf16.bf16.f32 "
        "{%0,%1,%2,%3}, {%4,%5,%6,%7}, {%8,%9}, {%0,%1,%2,%3};"
        : "+f"(d[0]), "+f"(d[1]), "+f"(d[2]), "+f"(d[3])
        : "r"(a[0]), "r"(a[1]), "r"(a[2]), "r"(a[3]), "r"(b[0]), "r"(b[1]));
}
__device__ __forceinline__ void ldm4(unsigned* r, unsigned addr) {
    asm("ldmatrix.sync.aligned.m8n8.x4.shared.b16 {%0,%1,%2,%3}, [%4];"
        : "=r"(r[0]), "=r"(r[1]), "=r"(r[2]), "=r"(r[3]) : "r"(addr));
}
__device__ __forceinline__ void cpa16(unsigned dst, const void* src) {
    asm volatile("cp.async.cg.shared.global [%0], [%1], 16;" :: "r"(dst), "l"(src));
}
__device__ __forceinline__ void cpa_commit() {
    asm volatile("cp.async.commit_group;" ::: "memory");
}
__device__ __forceinline__ unsigned smem_u32(const void* p) {
    unsigned a;
    asm("{ .reg .u64 t; cvta.to.shared.u64 t, %1; cvt.u32.u64 %0, t; }"
        : "=r"(a) : "l"(p));
    return a;
}
__device__ __forceinline__ float gelu_tanh(float x) {
    float x3 = x * x * x;
    return 0.5f * x * (1.f + tanhf(0.7978845608028654f * (x + 0.044715f * x3)));
}
__device__ __forceinline__ void splitpack2(float x0, float x1, unsigned& h, unsigned& l) {
    __nv_bfloat16 h0 = __float2bfloat16_rn(x0);
    __nv_bfloat16 h1 = __float2bfloat16_rn(x1);
    float r0 = x0 - __bfloat162float(h0);
    float r1 = x1 - __bfloat162float(h1);
    __nv_bfloat16 l0 = __float2bfloat16_rn(r0);
    __nv_bfloat16 l1 = __float2bfloat16_rn(r1);
    h = ((unsigned)__bfloat16_as_ushort(h1) << 16) | __bfloat16_as_ushort(h0);
    l = ((unsigned)__bfloat16_as_ushort(l1) << 16) | __bfloat16_as_ushort(l0);
}

// ---------------------------------------------------------------------------
// Weight pre-split (vectorized)
// ---------------------------------------------------------------------------
__global__ void pack_w(const float* __restrict__ w, unsigned* __restrict__ hi,
                       unsigned* __restrict__ lo, int K2, int N) {
    int e = blockIdx.z;
    w  += (size_t)e * K2 * 2 * N;
    hi += (size_t)e * K2 * N;
    lo += (size_t)e * K2 * N;
    int n4 = blockIdx.x * 256 + threadIdx.x;
    int k2 = blockIdx.y;
    if (n4 * 4 >= N) return;
    float4 x0 = *(const float4*)(w + (size_t)(2 * k2) * N + n4 * 4);
    float4 x1 = *(const float4*)(w + (size_t)(2 * k2 + 1) * N + n4 * 4);
    uint4 h, l;
    splitpack2(x0.x, x1.x, h.x, l.x);
    splitpack2(x0.y, x1.y, h.y, l.y);
    splitpack2(x0.z, x1.z, h.z, l.z);
    splitpack2(x0.w, x1.w, h.w, l.w);
    *(uint4*)(hi + (size_t)k2 * N + n4 * 4) = h;
    *(uint4*)(lo + (size_t)k2 * N + n4 * 4) = l;
}

// ---------------------------------------------------------------------------
// adaLN modulation
// ---------------------------------------------------------------------------
__global__ void adaln_kernel(const float* __restrict__ c,
                             const float* __restrict__ w,
                             const float* __restrict__ b) {
    int bb = blockIdx.y;
    int col = blockIdx.x * 128 + threadIdx.x;
    __shared__ float cs[DD];
    for (int i = threadIdx.x; i < DD; i += 128) {
        float v = c[bb * DD + i];
        cs[i] = v / (1.f + __expf(-v));
    }
    __syncthreads();
    float acc = b[col];
    #pragma unroll 4
    for (int i = 0; i < DD; i++)
        acc += cs[i] * w[(size_t)i * DD4 + col];
    g_mod[bb * DD4 + col] = acc;
}

// ---------------------------------------------------------------------------
// LayerNorm.
// MODE 0: packed(ln(x)*(1+scale)+shift) -> g_hh/g_hl
// MODE 1: packed ln(in) -> g_nxh/g_nxl  AND fused router (top-2 + softmax)
// ---------------------------------------------------------------------------
template <int MODE>
__global__ void ln_kernel(const float* __restrict__ in,
                          const float* __restrict__ gw,
                          const float* __restrict__ gb) {
    int t = blockIdx.x;
    const float* xr = in + (size_t)t * DD;
    int tid = threadIdx.x, lane = tid & 31, warp = tid >> 5;
    float s = 0.f, s2 = 0.f;
    for (int i = tid; i < DD; i += 256) { float v = xr[i]; s += v; s2 += v * v; }
    #pragma unroll
    for (int o = 16; o; o >>= 1) {
        s  += __shfl_xor_sync(0xffffffffu, s,  o);
        s2 += __shfl_xor_sync(0xffffffffu, s2, o);
    }
    __shared__ float ws[8], ws2[8], mean_s, rstd_s;
    __shared__ float wsl[8][NE];
    if (lane == 0) { ws[warp] = s; ws2[warp] = s2; }
    __syncthreads();
    if (warp == 0) {
        s  = (lane < 8) ? ws[lane]  : 0.f;
        s2 = (lane < 8) ? ws2[lane] : 0.f;
        #pragma unroll
        for (int o = 4; o; o >>= 1) {
            s  += __shfl_xor_sync(0xffffffffu, s,  o);
            s2 += __shfl_xor_sync(0xffffffffu, s2, o);
        }
        if (lane == 0) {
            float m = s * (1.f / DD);
            float v = s2 * (1.f / DD) - m * m;
            mean_s = m; rstd_s = rsqrtf(v + LN_EPS);
        }
    }
    __syncthreads();
    float m = mean_s, rstd = rstd_s;
    int bb = t >> 8;
    float accE[NE];
    if (MODE == 1) {
        #pragma unroll
        for (int e = 0; e < NE; e++) accE[e] = 0.f;
    }
    for (int i2 = tid; i2 < DD2; i2 += 256) {
        float v0 = (xr[2 * i2]     - m) * rstd;
        float v1 = (xr[2 * i2 + 1] - m) * rstd;
        if (MODE == 0) {
            const float* sc = g_mod + bb * DD4 + DD;
            const float* sh = g_mod + bb * DD4;
            v0 = v0 * (1.f + sc[2 * i2])     + sh[2 * i2];
            v1 = v1 * (1.f + sc[2 * i2 + 1]) + sh[2 * i2 + 1];
            unsigned h, l;
            splitpack2(v0, v1, h, l);
            g_hh[(size_t)t * DD2 + i2] = h;
            g_hl[(size_t)t * DD2 + i2] = l;
        } else {
            unsigned h, l;
            splitpack2(v0, v1, h, l);
            g_nxh[(size_t)t * DD2 + i2] = h;
            g_nxl[(size_t)t * DD2 + i2] = l;
            const float* g0 = gw + (size_t)(2 * i2) * NE;
            #pragma unroll
            for (int e = 0; e < NE; e++)
                accE[e] += v0 * g0[e] + v1 * g0[NE + e];
        }
    }
    if (MODE == 1) {
        // block-reduce 8 logits
        #pragma unroll
        for (int e = 0; e < NE; e++)
            #pragma unroll
            for (int o = 16; o; o >>= 1)
                accE[e] += __shfl_xor_sync(0xffffffffu, accE[e], o);
        if (lane == 0)
            #pragma unroll
            for (int e = 0; e < NE; e++) wsl[warp][e] = accE[e];
        __syncthreads();
        if (tid == 0) {
            float logit[NE];
            #pragma unroll
            for (int e = 0; e < NE; e++) {
                float a = 0.f;
                #pragma unroll
                for (int wq = 0; wq < 8; wq++) a += wsl[wq][e];
                logit[e] = a + gb[e];
            }
            float best = -1e30f, second = -1e30f; int bi = 0, si = 0;
            #pragma unroll
            for (int e = 0; e < NE; e++) {
                float v = logit[e];
                if (v > best) { second = best; si = bi; best = v; bi = e; }
                else if (v > second) { second = v; si = e; }
            }
            float e1 = __expf(second - best);
            float inv = 1.f / (1.f + e1);
            g_topidx[t * 2] = bi;  g_topidx[t * 2 + 1] = si;
            g_score[t * 2] = inv;  g_score[t * 2 + 1] = e1 * inv;
        }
    }
}

// ---------------------------------------------------------------------------
// bf16x3 GEMM, templated M-tile (128 or 64). cp.async, ldmatrix, 2 CTAs/SM.
// MODE 0: g_qkv = A @ qkv_w + b
// MODE 1: out = xres + gate_msa*(A@proj + b)
// MODE 2: g_h1(packed) = gelu(gather(nx)@w1 + b1)
// MODE 3: out[tok] += gate_mlp*score*(h1@w2 + b2)   (fused combine, atomic)
// ---------------------------------------------------------------------------
#define A_STRIDE 20
#define B_STRIDE 136
#define B_WORDS 2176   // 16 * 136

template <int MODE, int MTILE>
__global__ __launch_bounds__(256, 2)
void gemm_tc(const unsigned* __restrict__ Ah, const unsigned* __restrict__ Al,
             const unsigned* __restrict__ Wh, const unsigned* __restrict__ Wl,
             const float* __restrict__ bias,
             const float* __restrict__ xres, float* __restrict__ Cout,
             int M, int Nn, int Kk) {
    constexpr int A_WORDS = MTILE * A_STRIDE;
    constexpr int AL_OFF = A_WORDS;
    constexpr int BH_OFF = 2 * A_WORDS;
    constexpr int BL_OFF = 2 * A_WORDS + B_WORDS;
    constexpr int BUFW   = 2 * A_WORDS + 2 * B_WORDS;
    constexpr int MI = MTILE / 32;

    int e = blockIdx.z;
    const int* gather = nullptr;
    int rowbase = 0;
    float* C = Cout;

    if (MODE == 2) {
        M = g_cnt[e]; rowbase = g_off[e];
        gather = g_bucket_tok + rowbase;
        Wh += (size_t)e * DD2 * MH;
        Wl += (size_t)e * DD2 * MH;
        bias += e * MH;
    } else if (MODE == 3) {
        M = g_cnt[e]; rowbase = g_off[e];
        Ah += (size_t)rowbase * MH2;
        Al += (size_t)rowbase * MH2;
        Wh += (size_t)e * MH2 * DD;
        Wl += (size_t)e * MH2 * DD;
        bias += e * DD;
    } else if (MODE == 0) {
        C = g_qkv;
    }

    int row0 = blockIdx.y * MTILE;
    if (row0 >= M) return;
    int col0 = blockIdx.x * 128;

    extern __shared__ __align__(16) unsigned smu[];
    unsigned sb = smem_u32(smu);
    int K2 = Kk / 2;

    int tid = threadIdx.x;
    int lane = tid & 31, wid = tid >> 5;
    int gid = lane >> 2, tig = lane & 3;
    int wm = wid >> 2, wn = wid & 3;

    int r_a, sa;
    if (MTILE == 128) { r_a = tid >> 1; sa = (tid & 1) * 2; }
    else              { r_a = tid >> 2; sa = tid & 3; }
    int gr = row0 + r_a;
    if (gr > M - 1) gr = M - 1;
    size_t arow = (size_t)((MODE == 2) ? gather[gr] : gr) * K2;
    const unsigned* aSrcH = Ah + arow + sa * 4;
    const unsigned* aSrcL = Al + arow + sa * 4;
    unsigned aDstH = sb + (r_a * A_STRIDE + sa * 4) * 4;
    unsigned aDstL = sb + (AL_OFF + r_a * A_STRIDE + sa * 4) * 4;
    int r_b = tid >> 4, sbg = (tid & 15) * 2;
    const unsigned* bSrcH = Wh + (size_t)r_b * Nn + col0 + sbg * 4;
    const unsigned* bSrcL = Wl + (size_t)r_b * Nn + col0 + sbg * 4;
    unsigned bDstH = sb + (BH_OFF + r_b * B_STRIDE + sbg * 4) * 4;
    unsigned bDstL = sb + (BL_OFF + r_b * B_STRIDE + sbg * 4) * 4;

    float acc[MI][4][4];
    #pragma unroll
    for (int mi = 0; mi < MI; mi++)
        #pragma unroll
        for (int ni = 0; ni < 4; ni++)
            #pragma unroll
            for (int r = 0; r < 4; r++) acc[mi][ni][r] = 0.f;

    int nch = Kk / 32;
    {
        if (MTILE == 128) {
            cpa16(aDstH,      aSrcH);     cpa16(aDstH + 16, aSrcH + 4);
            cpa16(aDstL,      aSrcL);     cpa16(aDstL + 16, aSrcL + 4);
        } else {
            cpa16(aDstH, aSrcH);
            cpa16(aDstL, aSrcL);
        }
        cpa16(bDstH,      bSrcH);     cpa16(bDstH + 16, bSrcH + 4);
        cpa16(bDstL,      bSrcL);     cpa16(bDstL + 16, bSrcL + 4);
        cpa_commit();
    }

    int lrow = lane & 15;
    int lk = ((lane >> 4) & 1) * 4;
    unsigned aBaseH = sb + ((wm * (MTILE / 2) + lrow) * A_STRIDE + lk) * 4;

    for (int c = 0; c < nch; c++) {
        int cur = c & 1;
        bool more = (c + 1 < nch);
        if (more) {
            unsigned bo = (cur ^ 1) * (BUFW * 4);
            size_t ao = (size_t)(c + 1) * 16;
            size_t wo = (size_t)(c + 1) * 16 * Nn;
            if (MTILE == 128) {
                cpa16(aDstH + bo,      aSrcH + ao);  cpa16(aDstH + bo + 16, aSrcH + ao + 4);
                cpa16(aDstL + bo,      aSrcL + ao);  cpa16(aDstL + bo + 16, aSrcL + ao + 4);
            } else {
                cpa16(aDstH + bo, aSrcH + ao);
                cpa16(aDstL + bo, aSrcL + ao);
            }
            cpa16(bDstH + bo,      bSrcH + wo);  cpa16(bDstH + bo + 16, bSrcH + wo + 4);
            cpa16(bDstL + bo,      bSrcL + wo);  cpa16(bDstL + bo + 16, bSrcL + wo + 4);
            cpa_commit();
            asm volatile("cp.async.wait_group 1;" ::: "memory");
        } else {
            asm volatile("cp.async.wait_group 0;" ::: "memory");
        }
        __syncthreads();

        unsigned bufb = cur * (BUFW * 4);
        const unsigned* Bh = smu + cur * BUFW + BH_OFF;
        const unsigned* Bl = smu + cur * BUFW + BL_OFF;
        #pragma unroll
        for (int kb = 0; kb < 2; kb++) {
            unsigned afh[MI][4], afl[MI][4];
            unsigned bfh[4][2], bfl[4][2];
            #pragma unroll
            for (int mi = 0; mi < MI; mi++) {
                unsigned a = aBaseH + bufb + kb * 32 + mi * (16 * A_STRIDE * 4);
                ldm4(afh[mi], a);
                ldm4(afl[mi], a + AL_OFF * 4);
            }
            #pragma unroll
            for (int ni = 0; ni < 4; ni++) {
                int n = wn * 32 + ni * 8 + gid;
                int j0 = (kb * 8 + tig) * B_STRIDE + n;
                int j1 = (kb * 8 + tig + 4) * B_STRIDE + n;
                bfh[ni][0] = Bh[j0]; bfh[ni][1] = Bh[j1];
                bfl[ni][0] = Bl[j0]; bfl[ni][1] = Bl[j1];
            }
            #pragma unroll
            for (int mi = 0; mi < MI; mi++)
                #pragma unroll
                for (int ni = 0; ni < 4; ni++)
                    mma_bf16(acc[mi][ni], afl[mi], bfh[ni]);
            #pragma unroll
            for (int mi = 0; mi < MI; mi++)
                #pragma unroll
                for (int ni = 0; ni < 4; ni++)
                    mma_bf16(acc[mi][ni], afh[mi], bfl[ni]);
            #pragma unroll
            for (int mi = 0; mi < MI; mi++)
                #pragma unroll
                for (int ni = 0; ni < 4; ni++)
                    mma_bf16(acc[mi][ni], afh[mi], bfh[ni]);
        }
        __syncthreads();
    }

    #pragma unroll
    for (int mi = 0; mi < MI; mi++) {
        int mloc = row0 + wm * (MTILE / 2) + mi * 16 + gid;
        #pragma unroll
        for (int half = 0; half < 2; half++) {
            int m = mloc + half * 8;
            if (m >= M) continue;
            #pragma unroll
            for (int ni = 0; ni < 4; ni++) {
                int n = col0 + wn * 32 + ni * 8 + tig * 2;
                float ox = acc[mi][ni][half * 2 + 0] + bias[n];
                float oy = acc[mi][ni][half * 2 + 1] + bias[n + 1];
                if (MODE == 1) {
                    int bb = m >> 8;
                    const float* gm = g_mod + bb * DD4 + 2 * DD + n;
                    const float* rx = xres + (size_t)m * DD + n;
                    ox = rx[0] + gm[0] * ox;
                    oy = rx[1] + gm[1] * oy;
                    *(float2*)(C + (size_t)m * Nn + n) = make_float2(ox, oy);
                } else if (MODE == 2) {
                    ox = gelu_tanh(ox);
                    oy = gelu_tanh(oy);
                    unsigned h, l;
                    splitpack2(ox, oy, h, l);
                    size_t idx = (size_t)(rowbase + m) * (Nn / 2) + (n >> 1);
                    g_h1h[idx] = h;
                    g_h1l[idx] = l;
                } else if (MODE == 3) {
                    int slot = rowbase + m;
                    int t = g_bucket_tok[slot];
                    float s = g_slot_score[slot];
                    int bb = t >> 8;
                    const float* gm = g_mod + bb * DD4 + 3 * DD + n;
                    float* op = C + (size_t)t * DD + n;
                    atomicAdd(op,     s * gm[0] * ox);
                    atomicAdd(op + 1, s * gm[1] * oy);
                } else {
                    *(float2*)(C + (size_t)m * Nn + n) = make_float2(ox, oy);
                }
            }
        }
    }
}

// ---------------------------------------------------------------------------
// Attention: one block per (head, batch), 512 threads (16 warps, 4/SMSP).
// One shared K/V stage; each warp owns 16 queries (4 rounds of 4).
// Writes packed bf16 hi/lo output directly.
// ---------------------------------------------------------------------------
#define KV_STRIDE 74
#define ATTN_SMEM ((2 * 256 * KV_STRIDE + 16 * 4 * 256) * 4)   // 217088 B

__global__ __launch_bounds__(512, 1)
void attn_kernel() {
    int h = blockIdx.x, b = blockIdx.y;
    extern __shared__ float smn[];
    float* Ks = smn;
    float* Vs = smn + 256 * KV_STRIDE;
    float* Ps = smn + 2 * 256 * KV_STRIDE;    // [16 warps][4][256]

    const float* base = g_qkv + (size_t)b * SEQ * DD3;
    int tid = threadIdx.x;
    for (int i = tid; i < SEQ * (HD / 2); i += 512) {
        int r = i / (HD / 2), d2 = i - r * (HD / 2);
        size_t g = (size_t)r * DD3 + h * HD + 2 * d2;
        *(float2*)(Ks + r * KV_STRIDE + 2 * d2) = make_float2(base[g + DD],     base[g + DD + 1]);
        *(float2*)(Vs + r * KV_STRIDE + 2 * d2) = make_float2(base[g + 2 * DD], base[g + 2 * DD + 1]);
    }
    __syncthreads();

    int warp = tid >> 5, lane = tid & 31;
    float* ps = Ps + warp * 4 * 256;
    const float scale = 0.11785113019775793f;

    #pragma unroll
    for (int j = 0; j < 4; j++) {
        int q0 = j * 64 + warp * 4;

        float acc[4][8];
        #pragma unroll
        for (int i = 0; i < 4; i++)
            #pragma unroll
            for (int kk = 0; kk < 8; kk++) acc[i][kk] = 0.f;

        const float* q0p = base + (size_t)q0 * DD3 + h * HD;
        for (int d2 = 0; d2 < HD / 2; d2++) {
            float2 kd[8];
            #pragma unroll
            for (int kk = 0; kk < 8; kk++)
                kd[kk] = *(const float2*)(Ks + (lane + kk * 32) * KV_STRIDE + 2 * d2);
            float2 qd[4];
            #pragma unroll
            for (int i = 0; i < 4; i++)
                qd[i] = *(const float2*)(q0p + (size_t)i * DD3 + 2 * d2);
            #pragma unroll
            for (int i = 0; i < 4; i++)
                #pragma unroll
                for (int kk = 0; kk < 8; kk++)
                    acc[i][kk] += qd[i].x * kd[kk].x + qd[i].y * kd[kk].y;
        }

        #pragma unroll
        for (int i = 0; i < 4; i++) {
            float mx = -1e30f;
            #pragma unroll
            for (int kk = 0; kk < 8; kk++) {
                acc[i][kk] *= scale;
                mx = fmaxf(mx, acc[i][kk]);
            }
            #pragma unroll
            for (int o = 16; o; o >>= 1) mx = fmaxf(mx, __shfl_xor_sync(0xffffffffu, mx, o));
            float sum = 0.f;
            #pragma unroll
            for (int kk = 0; kk < 8; kk++) { acc[i][kk] = __expf(acc[i][kk] - mx); sum += acc[i][kk]; }
            #pragma unroll
            for (int o = 16; o; o >>= 1) sum += __shfl_xor_sync(0xffffffffu, sum, o);
            float inv = 1.f / sum;
            #pragma unroll
            for (int kk = 0; kk < 8; kk++) ps[i * 256 + lane + kk * 32] = acc[i][kk] * inv;
        }
        __syncwarp();

        float o0[4], o1[4], o2[4];
        #pragma unroll
        for (int i = 0; i < 4; i++) { o0[i] = 0.f; o1[i] = 0.f; o2[i] = 0.f; }
        for (int k = 0; k < SEQ; k++) {
            const float* vr = Vs + k * KV_STRIDE;
            float v0 = vr[lane];
            float v1 = vr[lane + 32];
            float v2 = (lane < 8) ? vr[lane + 64] : 0.f;
            #pragma unroll
            for (int i = 0; i < 4; i++) {
                float p = ps[i * 256 + k];
                o0[i] += p * v0;
                o1[i] += p * v1;
                o2[i] += p * v2;
            }
        }
        #pragma unroll
        for (int i = 0; i < 4; i++) {
            float p0 = __shfl_xor_sync(0xffffffffu, o0[i], 1);
            float p1 = __shfl_xor_sync(0xffffffffu, o1[i], 1);
            float p2 = __shfl_xor_sync(0xffffffffu, o2[i], 1);
            if ((lane & 1) == 0) {
                size_t rb = (size_t)(b * SEQ + q0 + i) * DD2 + h * (HD / 2);
                unsigned hw, lw;
                splitpack2(o0[i], p0, hw, lw);
                g_aoh[rb + (lane >> 1)] = hw;
                g_aol[rb + (lane >> 1)] = lw;
                splitpack2(o1[i], p1, hw, lw);
                g_aoh[rb + 16 + (lane >> 1)] = hw;
                g_aol[rb + 16 + (lane >> 1)] = lw;
                if (lane < 8) {
                    splitpack2(o2[i], p2, hw, lw);
                    g_aoh[rb + 32 + (lane >> 1)] = hw;
                    g_aol[rb + 32 + (lane >> 1)] = lw;
                }
            }
        }
        __syncwarp();
    }
}

// ---------------------------------------------------------------------------
// Bucketize (also writes slot -> score map)
// ---------------------------------------------------------------------------
__global__ void bucketize_kernel() {
    __shared__ int cnt[NE], off[NE], cur[NE];
    int tid = threadIdx.x;
    if (tid < NE) cnt[tid] = 0;
    __syncthreads();
    for (int t = tid; t < NTOK; t += 256) {
        atomicAdd(&cnt[g_topidx[t * 2]], 1);
        atomicAdd(&cnt[g_topidx[t * 2 + 1]], 1);
    }
    __syncthreads();
    if (tid == 0) {
        int o = 0;
        for (int e = 0; e < NE; e++) {
            off[e] = o; g_off[e] = o; g_cnt[e] = cnt[e];
            o += cnt[e];
        }
    }
    __syncthreads();
    if (tid < NE) cur[tid] = off[tid];
    __syncthreads();
    for (int t = tid; t < NTOK; t += 256) {
        #pragma unroll
        for (int k = 0; k < 2; k++) {
            int e = g_topidx[t * 2 + k];
            int p = atomicAdd(&cur[e], 1);
            g_bucket_tok[p] = t;
            g_slot_score[p] = g_score[t * 2 + k];
        }
    }
}

// ---------------------------------------------------------------------------
// Launcher
// ---------------------------------------------------------------------------
#define GEMM_SMEM_128 (2 * (2 * (128 * A_STRIDE) + 2 * B_WORDS) * 4)  // 75776
#define GEMM_SMEM_64  (2 * (2 * (64 * A_STRIDE) + 2 * B_WORDS) * 4)   // 55296

extern "C" void kernel_launch(void* const* d_in, const int* in_sizes, int n_in,
                              void* d_out, int out_size) {
    (void)in_sizes; (void)n_in; (void)out_size;
    const float* x       = (const float*)d_in[0];
    const float* c       = (const float*)d_in[1];
    const float* qkv_w   = (const float*)d_in[2];
    const float* qkv_b   = (const float*)d_in[3];
    const float* proj_w  = (const float*)d_in[4];
    const float* proj_b  = (const float*)d_in[5];
    const float* adaln_w = (const float*)d_in[6];
    const float* adaln_b = (const float*)d_in[7];
    const float* gate_w  = (const float*)d_in[8];
    const float* gate_b  = (const float*)d_in[9];
    const float* w1      = (const float*)d_in[10];
    const float* b1      = (const float*)d_in[11];
    const float* w2      = (const float*)d_in[12];
    const float* b2      = (const float*)d_in[13];
    float* out = (float*)d_out;

    static cudaStream_t s2 = nullptr;
    static cudaEvent_t evF = nullptr, evJ = nullptr;
    if (s2 == nullptr) {
        cudaStreamCreateWithFlags(&s2, cudaStreamNonBlocking);
        cudaEventCreateWithFlags(&evF, cudaEventDisableTiming);
        cudaEventCreateWithFlags(&evJ, cudaEventDisableTiming);
    }

    cudaFuncSetAttribute(attn_kernel, cudaFuncAttributeMaxDynamicSharedMemorySize, ATTN_SMEM);
    cudaFuncSetAttribute(gemm_tc<0,128>, cudaFuncAttributeMaxDynamicSharedMemorySize, GEMM_SMEM_128);
    cudaFuncSetAttribute(gemm_tc<1,64>,  cudaFuncAttributeMaxDynamicSharedMemorySize, GEMM_SMEM_64);
    cudaFuncSetAttribute(gemm_tc<2,128>, cudaFuncAttributeMaxDynamicSharedMemorySize, GEMM_SMEM_128);
    cudaFuncSetAttribute(gemm_tc<3,64>,  cudaFuncAttributeMaxDynamicSharedMemorySize, GEMM_SMEM_64);

    unsigned *qkvh, *qkvl, *projh, *projl, *w1h, *w1l, *w2h, *w2l;
    unsigned *hh, *hl, *aoh, *aol, *nxh, *nxl, *h1h, *h1l;
    cudaGetSymbolAddress((void**)&qkvh, g_qkvh);
    cudaGetSymbolAddress((void**)&qkvl, g_qkvl);
    cudaGetSymbolAddress((void**)&projh, g_projh);
    cudaGetSymbolAddress((void**)&projl, g_projl);
    cudaGetSymbolAddress((void**)&w1h, g_w1h);
    cudaGetSymbolAddress((void**)&w1l, g_w1l);
    cudaGetSymbolAddress((void**)&w2h, g_w2h);
    cudaGetSymbolAddress((void**)&w2l, g_w2l);
    cudaGetSymbolAddress((void**)&hh, g_hh);
    cudaGetSymbolAddress((void**)&hl, g_hl);
    cudaGetSymbolAddress((void**)&aoh, g_aoh);
    cudaGetSymbolAddress((void**)&aol, g_aol);
    cudaGetSymbolAddress((void**)&nxh, g_nxh);
    cudaGetSymbolAddress((void**)&nxl, g_nxl);
    cudaGetSymbolAddress((void**)&h1h, g_h1h);
    cudaGetSymbolAddress((void**)&h1l, g_h1l);

    // fork: big weight packs on side stream (fills any idle tails)
    cudaEventRecord(evF, 0);
    cudaStreamWaitEvent(s2, evF, 0);
    pack_w<<<dim3((MH / 4 + 255) / 256, DD2, NE), 256, 0, s2>>>(w1, w1h, w1l, DD2, MH);
    pack_w<<<dim3((DD / 4 + 255) / 256, MH2, NE), 256, 0, s2>>>(w2, w2h, w2l, MH2, DD);
    cudaEventRecord(evJ, s2);

    // main stream
    pack_w<<<dim3((DD3 / 4 + 255) / 256, DD2, 1), 256>>>(qkv_w, qkvh, qkvl, DD2, DD3);
    pack_w<<<dim3((DD / 4 + 255) / 256, DD2, 1),  256>>>(proj_w, projh, projl, DD2, DD);
    adaln_kernel<<<dim3(DD4 / 128, BATCH), 128>>>(c, adaln_w, adaln_b);
    ln_kernel<0><<<NTOK, 256>>>(x, nullptr, nullptr);
    gemm_tc<0,128><<<dim3(DD3 / 128, NTOK / 128, 1), 256, GEMM_SMEM_128>>>(
        hh, hl, qkvh, qkvl, qkv_b, nullptr, nullptr, NTOK, DD3, DD);
    attn_kernel<<<dim3(NH, BATCH), 512, ATTN_SMEM>>>();
    gemm_tc<1,64><<<dim3(DD / 128, NTOK / 64, 1), 256, GEMM_SMEM_64>>>(
        aoh, aol, projh, projl, proj_b, x, out, NTOK, DD, DD);
    ln_kernel<1><<<NTOK, 256>>>(out, gate_w, gate_b);
    bucketize_kernel<<<1, 256>>>();

    // join before MoE GEMMs consume w1/w2 packs
    cudaStreamWaitEvent(0, evJ, 0);
    gemm_tc<2,128><<<dim3(MH / 128, NTOK * 2 / 128, NE), 256, GEMM_SMEM_128>>>(
        nxh, nxl, w1h, w1l, b1, nullptr, nullptr, 0, MH, DD);
    gemm_tc<3,64><<<dim3(DD / 128, NTOK * 2 / 64, NE), 256, GEMM_SMEM_64>>>(
        h1h, h1l, w2h, w2l, b2, nullptr, out, 0, DD, MH);
}